// round 13
// baseline (speedup 1.0000x reference)
#include <cuda_runtime.h>
#include <cuda_bf16.h>
#include <cstdint>

// Problem constants (fixed by reference: B=4, C=256, CQ=32, H=W=64)
#define B_   4
#define C_   256
#define CQ_  32
#define N_   4096

typedef unsigned long long u64;

// Scratch (allocation-free rule: __device__ globals)
__device__ __nv_bfloat16 g_xt[B_ * N_ * C_];   // [B][N][C]   x transposed, bf16
__device__ __nv_bfloat16 g_q[B_ * N_ * CQ_];   // [B][N][CQ]  (masked, channel-contig)
__device__ __nv_bfloat16 g_k[B_ * N_ * CQ_];   // [B][N][CQ]  (masked, channel-contig)
__device__ __nv_bfloat16 g_v[B_ * C_ * N_];    // [B][C][N]   (key-contig)

// ---------------------------------------------------------------------------
// Helpers
// ---------------------------------------------------------------------------
__device__ __forceinline__ uint32_t pack_bf16(float lo, float hi) {
    __nv_bfloat162 h = __floats2bfloat162_rn(lo, hi);   // .x = lo (low 16 bits)
    return *(uint32_t*)&h;
}

// mma m16n8k16 bf16: D = A*B + D (fp32 accumulate)
__device__ __forceinline__ void mma16(float* d, const uint32_t* a,
                                      uint32_t b0, uint32_t b1) {
    asm("mma.sync.aligned.m16n8k16.row.col.f32.bf16.bf16.f32 "
        "{%0,%1,%2,%3},{%4,%5,%6,%7},{%8,%9},{%0,%1,%2,%3};"
        : "+f"(d[0]), "+f"(d[1]), "+f"(d[2]), "+f"(d[3])
        : "r"(a[0]), "r"(a[1]), "r"(a[2]), "r"(a[3]), "r"(b0), "r"(b1));
}

// cp.async helpers (.cg = L2-only streaming)
__device__ __forceinline__ void cp16(void* smem, const void* g) {
    unsigned s = (unsigned)__cvta_generic_to_shared(smem);
    asm volatile("cp.async.cg.shared.global [%0], [%1], 16;" :: "r"(s), "l"(g));
}
__device__ __forceinline__ void cp_commit() {
    asm volatile("cp.async.commit_group;");
}
template <int N>
__device__ __forceinline__ void cp_wait() {
    asm volatile("cp.async.wait_group %0;" :: "n"(N));
}

// ---------------------------------------------------------------------------
// Transpose + convert: x [b][c][n] f32 -> xt [b][n][c] bf16.
// ---------------------------------------------------------------------------
__global__ __launch_bounds__(256)
void transpose_cvt_kernel(const float* __restrict__ X,
                          __nv_bfloat16* __restrict__ xt)
{
    __shared__ float sm_t[128][33];
    const int b  = blockIdx.z;
    const int c0 = blockIdx.y * 32;
    const int n0 = blockIdx.x * 128;
    const int t  = threadIdx.x;

#pragma unroll
    for (int r = 0; r < 16; r++) {
        int idx = t + r * 256;
        int j = idx & 127, c = idx >> 7;
        sm_t[j][c] = X[((size_t)b * C_ + c0 + c) * N_ + n0 + j];
    }
    __syncthreads();

    const int j  = t >> 1;
    const int cc = (t & 1) * 16;
    uint32_t pk[8];
#pragma unroll
    for (int i = 0; i < 8; i++)
        pk[i] = pack_bf16(sm_t[j][cc + 2 * i], sm_t[j][cc + 2 * i + 1]);
    __nv_bfloat16* dst = xt + ((size_t)b * N_ + n0 + j) * C_ + c0 + cc;
    *(uint4*)dst       = *(uint4*)&pk[0];
    *(uint4*)(dst + 8) = *(uint4*)&pk[4];
}

// ---------------------------------------------------------------------------
// QK projection on tensor cores (validated @209us round).
// ---------------------------------------------------------------------------
#define XP_S 280
#define QKP_SMEM (128 * XP_S * 2 + 32 * XP_S * 2)

__global__ __launch_bounds__(256)
void qk_proj_kernel(const __nv_bfloat16* __restrict__ xt,
                    const float* __restrict__ Wq, const float* __restrict__ bq,
                    const float* __restrict__ Wk, const float* __restrict__ bk,
                    const float* __restrict__ mask,
                    __nv_bfloat16* __restrict__ outq,
                    __nv_bfloat16* __restrict__ outk)
{
    extern __shared__ __align__(16) char smr[];
    __nv_bfloat16* xs  = (__nv_bfloat16*)smr;                    // [128][280]
    __nv_bfloat16* wsm = (__nv_bfloat16*)(smr + 128 * XP_S * 2); // [32][280]

    const int b  = blockIdx.z;
    const int n0 = blockIdx.x * 128;
    const int t  = threadIdx.x;
    const bool isK = blockIdx.y != 0;
    const float* W    = isK ? Wk : Wq;
    const float* bias = isK ? bk : bq;
    __nv_bfloat16* out = isK ? outk : outq;

    const __nv_bfloat16* xp = xt + ((size_t)b * N_ + n0) * C_;
#pragma unroll
    for (int r = 0; r < 16; r++) {
        int idx = t + r * 256;
        int row = idx >> 5, ch = (idx & 31) * 8;
        cp16(xs + row * XP_S + ch, xp + (size_t)row * C_ + ch);
    }
    cp_commit();

#pragma unroll
    for (int r = 0; r < 8; r++) {
        int idx = t + r * 256;
        int o = idx >> 6, c4 = (idx & 63) * 4;
        float4 w = *(const float4*)(W + (size_t)o * C_ + c4);
        uint2 pk;
        pk.x = pack_bf16(w.x, w.y);
        pk.y = pack_bf16(w.z, w.w);
        *(uint2*)(wsm + o * XP_S + c4) = pk;
    }
    cp_wait<0>();
    __syncthreads();

    const int wid = t >> 5, lane = t & 31;
    const int gid = lane >> 2, tig = lane & 3;
    const int m0  = wid * 16;

    float s[4][4];
#pragma unroll
    for (int nt = 0; nt < 4; nt++)
#pragma unroll
        for (int r = 0; r < 4; r++) s[nt][r] = 0.f;

#pragma unroll
    for (int kt = 0; kt < 16; kt++) {
        const __nv_bfloat16* ar0 = xs + (m0 + gid)     * XP_S + kt * 16;
        const __nv_bfloat16* ar1 = xs + (m0 + gid + 8) * XP_S + kt * 16;
        uint32_t a[4];
        a[0] = *(const uint32_t*)(ar0 + 2 * tig);
        a[1] = *(const uint32_t*)(ar1 + 2 * tig);
        a[2] = *(const uint32_t*)(ar0 + 2 * tig + 8);
        a[3] = *(const uint32_t*)(ar1 + 2 * tig + 8);
#pragma unroll
        for (int nt = 0; nt < 4; nt++) {
            const __nv_bfloat16* br = wsm + (nt * 8 + gid) * XP_S + kt * 16;
            uint32_t b0 = *(const uint32_t*)(br + 2 * tig);
            uint32_t b1 = *(const uint32_t*)(br + 2 * tig + 8);
            mma16(s[nt], a, b0, b1);
        }
    }

    int nr0 = n0 + m0 + gid;
    int nr1 = nr0 + 8;
    float mk0 = mask[(size_t)b * N_ + nr0];
    float mk1 = mask[(size_t)b * N_ + nr1];
#pragma unroll
    for (int nt = 0; nt < 4; nt++) {
        int o = nt * 8 + 2 * tig;
        float b0v = bias[o], b1v = bias[o + 1];
        *(uint32_t*)(out + ((size_t)b * N_ + nr0) * CQ_ + o) =
            pack_bf16((s[nt][0] + b0v) * mk0, (s[nt][1] + b1v) * mk0);
        *(uint32_t*)(out + ((size_t)b * N_ + nr1) * CQ_ + o) =
            pack_bf16((s[nt][2] + b0v) * mk1, (s[nt][3] + b1v) * mk1);
    }
}

// ---------------------------------------------------------------------------
// V projection on tensor cores (validated @209us round).
// ---------------------------------------------------------------------------
#define VP_SMEM (128 * XP_S * 2 + 64 * XP_S * 2)

__global__ __launch_bounds__(256)
void v_proj_kernel(const __nv_bfloat16* __restrict__ xt,
                   const float* __restrict__ W, const float* __restrict__ bias,
                   __nv_bfloat16* __restrict__ out)
{
    extern __shared__ __align__(16) char smr[];
    __nv_bfloat16* xs  = (__nv_bfloat16*)smr;                    // [128][280]
    __nv_bfloat16* wsm = (__nv_bfloat16*)(smr + 128 * XP_S * 2); // [64][280]

    const int b  = blockIdx.z;
    const int o0 = blockIdx.y * 64;
    const int n0 = blockIdx.x * 128;
    const int t  = threadIdx.x;

    const __nv_bfloat16* xp = xt + ((size_t)b * N_ + n0) * C_;
#pragma unroll
    for (int r = 0; r < 16; r++) {
        int idx = t + r * 256;
        int row = idx >> 5, ch = (idx & 31) * 8;
        cp16(xs + row * XP_S + ch, xp + (size_t)row * C_ + ch);
    }
    cp_commit();

#pragma unroll
    for (int r = 0; r < 16; r++) {
        int idx = t + r * 256;
        int o = idx >> 6, c4 = (idx & 63) * 4;
        float4 w = *(const float4*)(W + (size_t)(o0 + o) * C_ + c4);
        uint2 pk;
        pk.x = pack_bf16(w.x, w.y);
        pk.y = pack_bf16(w.z, w.w);
        *(uint2*)(wsm + o * XP_S + c4) = pk;
    }
    cp_wait<0>();
    __syncthreads();

    const int wid = t >> 5, lane = t & 31;
    const int gid = lane >> 2, tig = lane & 3;
    const int m0  = (wid >> 1) * 16;
    const int nh  = (wid & 1) * 64;

    float s[8][4];
#pragma unroll
    for (int nt = 0; nt < 8; nt++)
#pragma unroll
        for (int r = 0; r < 4; r++) s[nt][r] = 0.f;

#pragma unroll
    for (int kt = 0; kt < 16; kt++) {
        const __nv_bfloat16* ar0 = wsm + (m0 + gid)     * XP_S + kt * 16;
        const __nv_bfloat16* ar1 = wsm + (m0 + gid + 8) * XP_S + kt * 16;
        uint32_t a[4];
        a[0] = *(const uint32_t*)(ar0 + 2 * tig);
        a[1] = *(const uint32_t*)(ar1 + 2 * tig);
        a[2] = *(const uint32_t*)(ar0 + 2 * tig + 8);
        a[3] = *(const uint32_t*)(ar1 + 2 * tig + 8);
#pragma unroll
        for (int nt = 0; nt < 8; nt++) {
            const __nv_bfloat16* br = xs + (nh + nt * 8 + gid) * XP_S + kt * 16;
            uint32_t b0 = *(const uint32_t*)(br + 2 * tig);
            uint32_t b1 = *(const uint32_t*)(br + 2 * tig + 8);
            mma16(s[nt], a, b0, b1);
        }
    }

    int or0 = o0 + m0 + gid;
    int or1 = or0 + 8;
    float b0v = bias[or0];
    float b1v = bias[or1];
#pragma unroll
    for (int nt = 0; nt < 8; nt++) {
        int n = n0 + nh + nt * 8 + 2 * tig;
        *(uint32_t*)(out + ((size_t)b * C_ + or0) * N_ + n) =
            pack_bf16(s[nt][0] + b0v, s[nt][1] + b0v);
        *(uint32_t*)(out + ((size_t)b * C_ + or1) * N_ + n) =
            pack_bf16(s[nt][2] + b1v, s[nt][3] + b1v);
    }
}

// ---------------------------------------------------------------------------
// Flash attention, bf16 m16n8k16, 512 threads (16 warps) per 64-query CTA
// for 2x occupancy. Warp grid: wq = wid>>2 (query tile), wk = wid&3 (key
// quarter) for GEMM1; channel slice ch0 = wid*16 for GEMM2.
// SMEM (bytes):
//  qs  [64][40]        @0      (5120)
//  ks  [2][64][40]     @5120   (10240)
//  pb  [64][72]        @15360  (9216)
//  vs  [2][256][72]    @24576  (73728)
//  msh/lsh/csh f32[64] @98304/98560/98816
//  pmax f32[4][64]     @99072  (1024)
//  psum f32[4][64]     @100096 (1024)
// total 101120 -> 2 CTAs/SM, 32 warps.
// ---------------------------------------------------------------------------
#define QS_S 40
#define KS_S 40
#define PB_S 72
#define VS_S 72
#define ATTN_SMEM_BYTES 101120
#define NTILES (N_ / 64)

__global__ __launch_bounds__(512, 2)
void attn_kernel(const __nv_bfloat16* __restrict__ q,
                 const __nv_bfloat16* __restrict__ k,
                 const __nv_bfloat16* __restrict__ v,
                 const float* __restrict__ x,
                 const float* __restrict__ gamma, float* __restrict__ out)
{
    extern __shared__ __align__(16) char smr[];
    __nv_bfloat16* qs  = (__nv_bfloat16*)(smr);
    __nv_bfloat16* ks0 = (__nv_bfloat16*)(smr + 5120);
    __nv_bfloat16* ks1 = (__nv_bfloat16*)(smr + 10240);
    __nv_bfloat16* pb  = (__nv_bfloat16*)(smr + 15360);
    __nv_bfloat16* vs0 = (__nv_bfloat16*)(smr + 24576);
    __nv_bfloat16* vs1 = (__nv_bfloat16*)(smr + 61440);
    float* msh   = (float*)(smr + 98304);
    float* lsh   = (float*)(smr + 98560);
    float* csh   = (float*)(smr + 98816);
    float* pmaxs = (float*)(smr + 99072);   // [4][64]
    float* psums = (float*)(smr + 100096);  // [4][64]

    const int b   = blockIdx.y;
    const int qb0 = blockIdx.x * 64;
    const int t   = threadIdx.x;

    const __nv_bfloat16* qp = q + ((size_t)b * N_ + qb0) * CQ_;
    const __nv_bfloat16* kp = k + (size_t)b * N_ * CQ_;
    const __nv_bfloat16* vp = v + (size_t)b * C_ * N_;

    // ---- preamble: q tile, init, prefetch tile 0 ----
    if (t < 256) {   // q: 64 rows x 64B (uint4 per 8 bf16)
        int qi = t >> 2, ch = (t & 3) * 8;
        *(uint4*)(qs + qi * QS_S + ch) = *(const uint4*)(qp + qi * CQ_ + ch);
    }
    if (t < 64) { msh[t] = -INFINITY; lsh[t] = 0.f; }
    {
        if (t < 256) {   // K tile 0: 64 keys x 64B
            int key = t >> 2, ch = (t & 3) * 8;
            cp16(ks0 + key * KS_S + ch, kp + key * CQ_ + ch);
        }
#pragma unroll
        for (int r = 0; r < 4; r++) {   // V tile 0: 256 ch x 128B
            int idx = t + r * 512;
            int c  = idx >> 3, k8 = (idx & 7) * 8;
            cp16(vs0 + c * VS_S + k8, vp + (size_t)c * N_ + k8);
        }
        cp_commit();
    }
    __syncthreads();   // qs visible

    // warp/fragment coordinates
    const int wid  = t >> 5;           // 0..15
    const int lane = t & 31;
    const int gid  = lane >> 2;        // 0..7
    const int tig  = lane & 3;         // 0..3
    const int wq   = wid >> 2;         // query-tile 0..3
    const int wk   = wid & 3;          // key-quarter 0..3
    const int m0   = wq * 16;
    const int n1   = wk * 16;          // 2 n-tiles for GEMM1
    const int ch0  = wid * 16;         // GEMM2 channel slice (2 n-tiles)
    const int row0 = m0 + gid;
    const int row1 = m0 + gid + 8;

    // preload Q A-fragments (tile-invariant)
    uint32_t qa[2][4];
#pragma unroll
    for (int kt = 0; kt < 2; kt++) {
        const __nv_bfloat16* qr0 = qs + row0 * QS_S + kt * 16;
        const __nv_bfloat16* qr1 = qs + row1 * QS_S + kt * 16;
        qa[kt][0] = *(const uint32_t*)(qr0 + 2 * tig);
        qa[kt][1] = *(const uint32_t*)(qr1 + 2 * tig);
        qa[kt][2] = *(const uint32_t*)(qr0 + 2 * tig + 8);
        qa[kt][3] = *(const uint32_t*)(qr1 + 2 * tig + 8);
    }

    // O accumulators: [m-tile][n-tile(2)][4]
    float oa[4][2][4];
#pragma unroll
    for (int mt = 0; mt < 4; mt++)
#pragma unroll
        for (int nt = 0; nt < 2; nt++)
#pragma unroll
            for (int r = 0; r < 4; r++) oa[mt][nt][r] = 0.f;

    for (int it = 0; it < NTILES; it++) {
        const __nv_bfloat16* ks = (it & 1) ? ks1 : ks0;
        const __nv_bfloat16* vs = (it & 1) ? vs1 : vs0;

        cp_wait<0>();
        __syncthreads();   // A: tiles ready, prev GEMM2 done (pb free)

        // prefetch tile it+1
        if (it + 1 < NTILES) {
            __nv_bfloat16* ksn = (it & 1) ? ks0 : ks1;
            __nv_bfloat16* vsn = (it & 1) ? vs0 : vs1;
            int j0n = (it + 1) * 64;
            if (t < 256) {
                int key = t >> 2, ch = (t & 3) * 8;
                cp16(ksn + key * KS_S + ch, kp + (size_t)(j0n + key) * CQ_ + ch);
            }
#pragma unroll
            for (int r = 0; r < 4; r++) {
                int idx = t + r * 512;
                int c  = idx >> 3, k8 = (idx & 7) * 8;
                cp16(vsn + c * VS_S + k8, vp + (size_t)c * N_ + j0n + k8);
            }
            cp_commit();
        }

        // ---- GEMM1: S[16q x 16k] per warp (2 n-tiles) ----
        float s[2][4];
#pragma unroll
        for (int nt = 0; nt < 2; nt++)
#pragma unroll
            for (int r = 0; r < 4; r++) s[nt][r] = 0.f;
#pragma unroll
        for (int kt = 0; kt < 2; kt++) {
#pragma unroll
            for (int nt = 0; nt < 2; nt++) {
                const __nv_bfloat16* kr = ks + (n1 + nt * 8 + gid) * KS_S + kt * 16;
                uint32_t b0 = *(const uint32_t*)(kr + 2 * tig);
                uint32_t b1 = *(const uint32_t*)(kr + 2 * tig + 8);
                mma16(s[nt], qa[kt], b0, b1);
            }
        }

        // warp-level row max over this warp's 16 keys
        float mx0 = fmaxf(fmaxf(s[0][0], s[0][1]), fmaxf(s[1][0], s[1][1]));
        float mx1 = fmaxf(fmaxf(s[0][2], s[0][3]), fmaxf(s[1][2], s[1][3]));
        mx0 = fmaxf(mx0, __shfl_xor_sync(0xffffffffu, mx0, 1));
        mx0 = fmaxf(mx0, __shfl_xor_sync(0xffffffffu, mx0, 2));
        mx1 = fmaxf(mx1, __shfl_xor_sync(0xffffffffu, mx1, 1));
        mx1 = fmaxf(mx1, __shfl_xor_sync(0xffffffffu, mx1, 2));
        if (tig == 0) {
            pmaxs[wk * 64 + row0] = mx0;
            pmaxs[wk * 64 + row1] = mx1;
        }
        // read old maxes BEFORE barrier B (writers update after B)
        float mo0 = msh[row0];
        float mo1 = msh[row1];
        __syncthreads();   // B: pmax ready

        // ---- softmax on registers ----
        {
            float fx0 = fmaxf(fmaxf(fmaxf(pmaxs[row0], pmaxs[64 + row0]),
                                    fmaxf(pmaxs[128 + row0], pmaxs[192 + row0])), mo0);
            float fx1 = fmaxf(fmaxf(fmaxf(pmaxs[row1], pmaxs[64 + row1]),
                                    fmaxf(pmaxs[128 + row1], pmaxs[192 + row1])), mo1);
            float sum0 = 0.f, sum1 = 0.f;
#pragma unroll
            for (int nt = 0; nt < 2; nt++) {
                float p0 = __expf(s[nt][0] - fx0);
                float p1 = __expf(s[nt][1] - fx0);
                float p2 = __expf(s[nt][2] - fx1);
                float p3 = __expf(s[nt][3] - fx1);
                int jc = n1 + nt * 8 + 2 * tig;
                *(uint32_t*)(pb + row0 * PB_S + jc) = pack_bf16(p0, p1);
                *(uint32_t*)(pb + row1 * PB_S + jc) = pack_bf16(p2, p3);
                sum0 += p0 + p1;
                sum1 += p2 + p3;
            }
            sum0 += __shfl_xor_sync(0xffffffffu, sum0, 1);
            sum0 += __shfl_xor_sync(0xffffffffu, sum0, 2);
            sum1 += __shfl_xor_sync(0xffffffffu, sum1, 1);
            sum1 += __shfl_xor_sync(0xffffffffu, sum1, 2);
            if (tig == 0) {
                psums[wk * 64 + row0] = sum0;
                psums[wk * 64 + row1] = sum1;
                if (wk == 0) {
                    msh[row0] = fx0;  csh[row0] = __expf(mo0 - fx0);
                    msh[row1] = fx1;  csh[row1] = __expf(mo1 - fx1);
                }
            }
        }
        __syncthreads();   // C: pb, psum, csh ready

        // ---- l update + O rescale + GEMM2 ----
        if (t < 64)
            lsh[t] = lsh[t] * csh[t] +
                     (psums[t] + psums[64 + t]) + (psums[128 + t] + psums[192 + t]);
#pragma unroll
        for (int mt = 0; mt < 4; mt++) {
            float cr0 = csh[mt * 16 + gid];
            float cr1 = csh[mt * 16 + gid + 8];
#pragma unroll
            for (int nt = 0; nt < 2; nt++) {
                oa[mt][nt][0] *= cr0; oa[mt][nt][1] *= cr0;
                oa[mt][nt][2] *= cr1; oa[mt][nt][3] *= cr1;
            }
        }
#pragma unroll
        for (int kt = 0; kt < 4; kt++) {
            uint32_t vb[2][2];
#pragma unroll
            for (int nt = 0; nt < 2; nt++) {
                const __nv_bfloat16* vr = vs + (ch0 + nt * 8 + gid) * VS_S + kt * 16;
                vb[nt][0] = *(const uint32_t*)(vr + 2 * tig);
                vb[nt][1] = *(const uint32_t*)(vr + 2 * tig + 8);
            }
#pragma unroll
            for (int mt = 0; mt < 4; mt++) {
                const __nv_bfloat16* pr0 = pb + (mt * 16 + gid) * PB_S + kt * 16;
                const __nv_bfloat16* pr1 = pb + (mt * 16 + gid + 8) * PB_S + kt * 16;
                uint32_t pA[4];
                pA[0] = *(const uint32_t*)(pr0 + 2 * tig);
                pA[1] = *(const uint32_t*)(pr1 + 2 * tig);
                pA[2] = *(const uint32_t*)(pr0 + 2 * tig + 8);
                pA[3] = *(const uint32_t*)(pr1 + 2 * tig + 8);
#pragma unroll
                for (int nt = 0; nt < 2; nt++)
                    mma16(oa[mt][nt], pA, vb[nt][0], vb[nt][1]);
            }
        }
        // no trailing barrier: next iter's barrier A protects pb/vs
    }
    __syncthreads();   // lsh stable

    // ---- epilogue: out = gamma * O / l + x ----
    float g = gamma[0];
#pragma unroll
    for (int mt = 0; mt < 4; mt++) {
        float il0 = 1.f / lsh[mt * 16 + gid];
        float il1 = 1.f / lsh[mt * 16 + gid + 8];
        int r0 = qb0 + mt * 16 + gid;
        int r1 = r0 + 8;
#pragma unroll
        for (int nt = 0; nt < 2; nt++) {
            int c = ch0 + nt * 8 + 2 * tig;
            const float* x0 = x + ((size_t)b * C_ + c) * N_;
            float*       o0 = out + ((size_t)b * C_ + c) * N_;
            o0[r0]      = g * oa[mt][nt][0] * il0 + x0[r0];
            o0[N_ + r0] = g * oa[mt][nt][1] * il0 + x0[N_ + r0];
            o0[r1]      = g * oa[mt][nt][2] * il1 + x0[r1];
            o0[N_ + r1] = g * oa[mt][nt][3] * il1 + x0[N_ + r1];
        }
    }
}

// ---------------------------------------------------------------------------
// Launch
// ---------------------------------------------------------------------------
extern "C" void kernel_launch(void* const* d_in, const int* in_sizes, int n_in,
                              void* d_out, int out_size)
{
    const float* x     = (const float*)d_in[0];
    const float* mask  = (const float*)d_in[1];
    const float* Wq    = (const float*)d_in[2];
    const float* bq    = (const float*)d_in[3];
    const float* Wk    = (const float*)d_in[4];
    const float* bk    = (const float*)d_in[5];
    const float* Wv    = (const float*)d_in[6];
    const float* bv    = (const float*)d_in[7];
    const float* gamma = (const float*)d_in[8];
    float* out = (float*)d_out;

    __nv_bfloat16 *gxt, *gq, *gk, *gv;
    cudaGetSymbolAddress((void**)&gxt, g_xt);
    cudaGetSymbolAddress((void**)&gq, g_q);
    cudaGetSymbolAddress((void**)&gk, g_k);
    cudaGetSymbolAddress((void**)&gv, g_v);

    cudaFuncSetAttribute(qk_proj_kernel,
                         cudaFuncAttributeMaxDynamicSharedMemorySize, QKP_SMEM);
    cudaFuncSetAttribute(v_proj_kernel,
                         cudaFuncAttributeMaxDynamicSharedMemorySize, VP_SMEM);
    cudaFuncSetAttribute(attn_kernel,
                         cudaFuncAttributeMaxDynamicSharedMemorySize,
                         ATTN_SMEM_BYTES);

    transpose_cvt_kernel<<<dim3(N_ / 128, C_ / 32, B_), 256>>>(x, gxt);
    qk_proj_kernel<<<dim3(N_ / 128, 2, B_), 256, QKP_SMEM>>>(gxt, Wq, bq, Wk, bk, mask, gq, gk);
    v_proj_kernel <<<dim3(N_ / 128, C_ / 64, B_), 256, VP_SMEM>>>(gxt, Wv, bv, gv);
    attn_kernel<<<dim3(N_ / 64, B_), 512, ATTN_SMEM_BYTES>>>(gq, gk, gv, x, gamma, out);
}